// round 9
// baseline (speedup 1.0000x reference)
#include <cuda_runtime.h>

// MultiLayerRNNModel: 2-layer tanh RNN, T=2048, B=4096, I=3, H=5
// out = concat(out[T,B,H], h_n[2,B,H])
//
// R9: zero-communication, cross-layer-packed f32x2. Every lane redundantly
// computes the full 2-layer step for one batch (4 lanes/batch for store/load
// coalescing). Unit j's layer-0 and layer-1 pre-activations share one f32x2:
//   lo(A_j) = b0_j + sum_m wh0[j,m] h0_m(t-1) + sum_i wi0[j,i] x_i(t)
//   hi(A_j) = b1_j + sum_m wi1[j,m] h0_m(t-1) + sum_i wh1[j,i] h1_i(t-2)
// via WH[j][m]=(wh0,wi1)*splat(h0_m), WX[j][i]=(wi0|0, wh1)*(x_i, h1_i).
// Software pipelined: step t -> h0(t), h1(t-1). The recurrence chain is
// pure register FMA+MUFU -> no SHFL/STS/LDS/BAR (R2-R8 all choked on MIO).
// 128 blocks x 128 threads = 512 warps = exactly 1 warp per SMSP: the FMA
// pipe (60 fma2 * rt2 = 120cyc) is private per warp and is the only binder.

#define T_LEN   2048
#define B_SZ    4096
#define XSTRIDE (B_SZ * 3)
#define OSTRIDE (B_SZ * 5)

typedef unsigned long long ull;

__device__ __forceinline__ float tanh_fast(float v) {
    float y;
    asm("tanh.approx.f32 %0, %1;" : "=f"(y) : "f"(v));
    return y;
}
__device__ __forceinline__ ull pk2(float lo, float hi) {
    ull r;
    asm("mov.b64 %0, {%1, %2};" : "=l"(r) : "f"(lo), "f"(hi));
    return r;
}
__device__ __forceinline__ ull splat2(float v) { return pk2(v, v); }
__device__ __forceinline__ ull fma2(ull a, ull b, ull c) {
    ull d;
    asm("fma.rn.f32x2 %0, %1, %2, %3;" : "=l"(d) : "l"(a), "l"(b), "l"(c));
    return d;
}
__device__ __forceinline__ ull mul2(ull a, ull b) {
    ull d;
    asm("mul.rn.f32x2 %0, %1, %2;" : "=l"(d) : "l"(a), "l"(b));
    return d;
}
__device__ __forceinline__ ull add2(ull a, ull b) {
    ull d;
    asm("add.rn.f32x2 %0, %1, %2;" : "=l"(d) : "l"(a), "l"(b));
    return d;
}
__device__ __forceinline__ void unpk2(ull v, float& lo, float& hi) {
    asm("mov.b64 {%0, %1}, %2;" : "=f"(lo), "=f"(hi) : "l"(v));
}

__global__ __launch_bounds__(128, 1)
void rnn2_kernel(const float* __restrict__ x,
                 const float* __restrict__ hx,
                 const float* __restrict__ w_ih0,
                 const float* __restrict__ w_hh0,
                 const float* __restrict__ b_ih0,
                 const float* __restrict__ b_hh0,
                 const float* __restrict__ w_ih1,
                 const float* __restrict__ w_hh1,
                 const float* __restrict__ b_ih1,
                 const float* __restrict__ b_hh1,
                 float* __restrict__ out)
{
    const int k   = threadIdx.x & 3;            // lane-in-group: store role
    const int grp = threadIdx.x >> 2;           // 0..31
    const int b   = blockIdx.x * 32 + grp;      // exact: 128*32 = 4096

    // ---- packed weights (identical in all lanes) ----
    ull WH[5][5], WX[5][5], Bp[5];
    #pragma unroll
    for (int j = 0; j < 5; j++) {
        #pragma unroll
        for (int m = 0; m < 5; m++)
            WH[j][m] = pk2(w_hh0[j * 5 + m], w_ih1[j * 5 + m]);
        #pragma unroll
        for (int i = 0; i < 3; i++)
            WX[j][i] = pk2(w_ih0[j * 3 + i], w_hh1[j * 5 + i]);
        WX[j][3] = pk2(0.f, w_hh1[j * 5 + 3]);
        WX[j][4] = pk2(0.f, w_hh1[j * 5 + 4]);
        Bp[j] = pk2(b_ih0[j] + b_hh0[j], b_ih1[j] + b_hh1[j]);
    }

    // ---- state ----
    float h0c[5], h1c[5];                       // scalar h0(t-1), h1(t-2)
    ull S[5], O[5];                             // packed operands
    #pragma unroll
    for (int m = 0; m < 5; m++) {
        h0c[m] = hx[b * 5 + m];
        h1c[m] = hx[B_SZ * 5 + b * 5 + m];
        S[m] = splat2(h0c[m]);
    }

    const float* xb = x + b * 3;
    float* outp  = out + b * 5 + k;             // this lane's unit-k column
    float* outp4 = out + b * 5 + 4;             // lane 0 also stores unit 4

    // x prefetch queue, slot p holds x(t) with t&7 == p
    float xq[8][3];
    #pragma unroll
    for (int p = 0; p < 8; p++) {
        const float* xp = xb + p * XSTRIDE;
        xq[p][0] = xp[0]; xq[p][1] = xp[1]; xq[p][2] = xp[2];
    }
    // O holds (x_i(t), h1_i(t-2)); slots 3,4 lo-half is multiplied by 0
    #pragma unroll
    for (int i = 0; i < 3; i++) O[i] = pk2(xq[0][i], h1c[i]);
    O[3] = splat2(h1c[3]);
    O[4] = splat2(h1c[4]);

    ull A[5];

// Packed dual-layer pre-activation tree (3-way split, depth ~4 fma2).
#define TREES() {                                                             \
    _Pragma("unroll")                                                         \
    for (int j = 0; j < 5; j++) {                                             \
        ull t1 = fma2(WH[j][1], S[1], fma2(WH[j][0], S[0], Bp[j]));           \
        t1 = fma2(WH[j][2], S[2], t1);                                        \
        ull t2 = fma2(WH[j][4], S[4], mul2(WH[j][3], S[3]));                  \
        t2 = fma2(WX[j][0], O[0], t2);                                        \
        ull t3 = fma2(WX[j][2], O[2], mul2(WX[j][1], O[1]));                  \
        t3 = fma2(WX[j][3], O[3], t3);                                        \
        t3 = fma2(WX[j][4], O[4], t3);                                        \
        A[j] = add2(t1, add2(t2, t3));                                        \
    }                                                                         \
}

// One pipelined step t: h0(t) (lo) and h1(t-1) (hi). XP = t&7, XPn = (t+1)&7.
#define STEP(t, XP, XPn) {                                                    \
    TREES();                                                                  \
    float s0, s1, s2, s3, s4, u0, u1, u2, u3, u4;                             \
    unpk2(A[0], s0, u0); unpk2(A[1], s1, u1); unpk2(A[2], s2, u2);            \
    unpk2(A[3], s3, u3); unpk2(A[4], s4, u4);                                 \
    /* L0 tanhs first: they feed the next step's critical chain */           \
    h0c[0] = tanh_fast(s0); h0c[1] = tanh_fast(s1); h0c[2] = tanh_fast(s2);   \
    h0c[3] = tanh_fast(s3); h0c[4] = tanh_fast(s4);                           \
    h1c[0] = tanh_fast(u0); h1c[1] = tanh_fast(u1); h1c[2] = tanh_fast(u2);   \
    h1c[3] = tanh_fast(u3); h1c[4] = tanh_fast(u4);                           \
    S[0] = splat2(h0c[0]); S[1] = splat2(h0c[1]); S[2] = splat2(h0c[2]);      \
    S[3] = splat2(h0c[3]); S[4] = splat2(h0c[4]);                             \
    if ((t) + 8 < T_LEN) {                                                    \
        const float* xp = xb + ((t) + 8) * XSTRIDE;                           \
        xq[XP][0] = xp[0]; xq[XP][1] = xp[1]; xq[XP][2] = xp[2];              \
    }                                                                         \
    O[0] = pk2(xq[XPn][0], h1c[0]);                                           \
    O[1] = pk2(xq[XPn][1], h1c[1]);                                           \
    O[2] = pk2(xq[XPn][2], h1c[2]);                                           \
    O[3] = splat2(h1c[3]);                                                    \
    O[4] = splat2(h1c[4]);                                                    \
    const float hs = (k == 1) ? h1c[1] : (k == 2) ? h1c[2]                    \
                   : (k == 3) ? h1c[3] : h1c[0];                              \
    outp[((t) - 1) * OSTRIDE] = hs;                                           \
    if (k == 0) outp4[((t) - 1) * OSTRIDE] = h1c[4];                          \
}

    // ---- prologue t = 0: take h0(0) only; keep h1c = hx1 = h1(-1) ----
    {
        TREES();
        float s0, s1, s2, s3, s4, dmy;
        unpk2(A[0], s0, dmy); unpk2(A[1], s1, dmy); unpk2(A[2], s2, dmy);
        unpk2(A[3], s3, dmy); unpk2(A[4], s4, dmy);
        h0c[0] = tanh_fast(s0); h0c[1] = tanh_fast(s1);
        h0c[2] = tanh_fast(s2); h0c[3] = tanh_fast(s3);
        h0c[4] = tanh_fast(s4);
        #pragma unroll
        for (int m = 0; m < 5; m++) S[m] = splat2(h0c[m]);
        {   // refill phase 0 with x(8)
            const float* xp = xb + 8 * XSTRIDE;
            xq[0][0] = xp[0]; xq[0][1] = xp[1]; xq[0][2] = xp[2];
        }
        O[0] = pk2(xq[1][0], h1c[0]);
        O[1] = pk2(xq[1][1], h1c[1]);
        O[2] = pk2(xq[1][2], h1c[2]);
        // O[3], O[4] already splat2(hx1) from init
    }

    // ---- main loop: t = 1 .. 2040 (t0 = 8m+1) ----
    for (int t0 = 1; t0 < 2041; t0 += 8) {
        STEP(t0 + 0, 1, 2);
        STEP(t0 + 1, 2, 3);
        STEP(t0 + 2, 3, 4);
        STEP(t0 + 3, 4, 5);
        STEP(t0 + 4, 5, 6);
        STEP(t0 + 5, 6, 7);
        STEP(t0 + 6, 7, 0);
        STEP(t0 + 7, 0, 1);
    }
    // ---- tail: t = 2041 .. 2047 ----
    STEP(2041, 1, 2);
    STEP(2042, 2, 3);
    STEP(2043, 3, 4);
    STEP(2044, 4, 5);
    STEP(2045, 5, 6);
    STEP(2046, 6, 7);
    STEP(2047, 7, 0);

    // ---- epilogue: h1(2047) from S = h0(2047), O hi = h1(2046) ----
    {
        TREES();
        float dmy, u0, u1, u2, u3, u4;
        unpk2(A[0], dmy, u0); unpk2(A[1], dmy, u1); unpk2(A[2], dmy, u2);
        unpk2(A[3], dmy, u3); unpk2(A[4], dmy, u4);
        const float m0 = tanh_fast(u0), m1 = tanh_fast(u1),
                    m2 = tanh_fast(u2), m3 = tanh_fast(u3),
                    m4 = tanh_fast(u4);
        const float hs = (k == 1) ? m1 : (k == 2) ? m2 : (k == 3) ? m3 : m0;
        const float h0s = (k == 1) ? h0c[1] : (k == 2) ? h0c[2]
                        : (k == 3) ? h0c[3] : h0c[0];
        outp[(T_LEN - 1) * OSTRIDE] = hs;                       // out[2047]
        outp[(size_t)T_LEN * OSTRIDE] = h0s;                    // h_n[0]
        outp[(size_t)T_LEN * OSTRIDE + OSTRIDE] = hs;           // h_n[1]
        if (k == 0) {
            outp4[(T_LEN - 1) * OSTRIDE] = m4;
            outp4[(size_t)T_LEN * OSTRIDE] = h0c[4];
            outp4[(size_t)T_LEN * OSTRIDE + OSTRIDE] = m4;
        }
    }
#undef STEP
#undef TREES
}

extern "C" void kernel_launch(void* const* d_in, const int* in_sizes, int n_in,
                              void* d_out, int out_size)
{
    const float* x     = (const float*)d_in[0];
    const float* hx    = (const float*)d_in[1];
    const float* w_ih0 = (const float*)d_in[2];
    const float* w_hh0 = (const float*)d_in[3];
    const float* b_ih0 = (const float*)d_in[4];
    const float* b_hh0 = (const float*)d_in[5];
    const float* w_ih1 = (const float*)d_in[6];
    const float* w_hh1 = (const float*)d_in[7];
    const float* b_ih1 = (const float*)d_in[8];
    const float* b_hh1 = (const float*)d_in[9];
    float* out = (float*)d_out;

    // 128 blocks x 128 threads = 512 warps: one block per SM, one warp per
    // SMSP; 32 batches per block (4 lanes each).
    rnn2_kernel<<<128, 128>>>(x, hx, w_ih0, w_hh0, b_ih0, b_hh0,
                              w_ih1, w_hh1, b_ih1, b_hh1, out);
}

// round 10
// speedup vs baseline: 1.6210x; 1.6210x over previous
#include <cuda_runtime.h>

// MultiLayerRNNModel: 2-layer tanh RNN, T=2048, B=4096, I=3, H=5
// out = concat(out[T,B,H], h_n[2,B,H])
//
// R10: two kernels.
//  A) pre0[t,b,j] = (b_ih0+b_hh0)_j + W_ih0[j,:].x[t,b,:]  (DRAM-bound,
//     float4 in/out, ~268MB traffic) into a __device__ scratch array.
//  B) recurrence, R3 geometry (8 lanes/batch, 147x224 = 1024+ warps) but on
//     an LSU diet: 1 LDG (pre0) + 1 STS.64 (h0,h1 pair) + 3 LDS + 1 STG
//     per warp-step (was 10 warp-ops). Layers software-pipelined
//     (step t -> h0(t), h1(t-1)), one __syncwarp per step, double-buffered
//     slab with interleaved (h0_k,h1_k) pairs.

#define T_LEN   2048
#define B_SZ    4096
#define OSTRIDE (B_SZ * 5)

__device__ float g_pre0[(size_t)T_LEN * B_SZ * 5];

__device__ __forceinline__ float tanh_fast(float v) {
    float y;
    asm("tanh.approx.f32 %0, %1;" : "=f"(y) : "f"(v));
    return y;
}

// ---------------- Kernel A: pre0 = bias0 + x . W_ih0^T ----------------
// Each thread handles 4 consecutive (t,b) pairs: 12 input floats (3 float4
// loads), 20 output floats (5 float4 stores). 2048*4096/4 = 2,097,152 thr.
__global__ __launch_bounds__(256)
void pre0_kernel(const float* __restrict__ x,
                 const float* __restrict__ w_ih0,
                 const float* __restrict__ b_ih0,
                 const float* __restrict__ b_hh0)
{
    const int i = blockIdx.x * 256 + threadIdx.x;   // 0 .. 2097151

    float w[5][3], bias[5];
    #pragma unroll
    for (int j = 0; j < 5; j++) {
        bias[j] = b_ih0[j] + b_hh0[j];
        w[j][0] = w_ih0[j * 3 + 0];
        w[j][1] = w_ih0[j * 3 + 1];
        w[j][2] = w_ih0[j * 3 + 2];
    }

    const float4* xin = (const float4*)x + (size_t)i * 3;
    const float4 X0 = xin[0], X1 = xin[1], X2 = xin[2];
    const float xs[12] = {X0.x, X0.y, X0.z, X0.w,
                          X1.x, X1.y, X1.z, X1.w,
                          X2.x, X2.y, X2.z, X2.w};

    float o[20];
    #pragma unroll
    for (int u = 0; u < 4; u++) {
        const float a0 = xs[3 * u], a1 = xs[3 * u + 1], a2 = xs[3 * u + 2];
        #pragma unroll
        for (int j = 0; j < 5; j++)
            o[5 * u + j] = fmaf(w[j][2], a2,
                           fmaf(w[j][1], a1,
                           fmaf(w[j][0], a0, bias[j])));
    }

    float4* op = (float4*)g_pre0 + (size_t)i * 5;
    op[0] = make_float4(o[0],  o[1],  o[2],  o[3]);
    op[1] = make_float4(o[4],  o[5],  o[6],  o[7]);
    op[2] = make_float4(o[8],  o[9],  o[10], o[11]);
    op[3] = make_float4(o[12], o[13], o[14], o[15]);
    op[4] = make_float4(o[16], o[17], o[18], o[19]);
}

// ---------------- Kernel B: the recurrence ----------------
__global__ __launch_bounds__(224, 1)
void rnn_rec_kernel(const float* __restrict__ hx,
                    const float* __restrict__ w_hh0,
                    const float* __restrict__ w_ih1,
                    const float* __restrict__ w_hh1,
                    const float* __restrict__ b_ih1,
                    const float* __restrict__ b_hh1,
                    float* __restrict__ out)
{
    // Slot layout (20-float stride, conflict-free LDS.128 bases 0/20/8/28):
    //   [2k] = h0_k, [2k+1] = h1_k for k=0..4; [10..19] pad (j>=5 writes).
    __shared__ __align__(16) float buf[2][28][20];

    const int tid = blockIdx.x * 224 + threadIdx.x;
    const int b   = tid >> 3;
    const int j   = threadIdx.x & 7;
    const int g   = threadIdx.x >> 3;
    const bool bval = (b < B_SZ);
    const bool act  = bval && (j < 5);
    const int  jj   = (j < 5) ? j : 0;

    // per-lane weights (row jj)
    float wh0[5], wi1[5], wh1[5];
    #pragma unroll
    for (int k = 0; k < 5; k++) {
        wh0[k] = w_hh0[jj * 5 + k];
        wi1[k] = w_ih1[jj * 5 + k];
        wh1[k] = w_hh1[jj * 5 + k];
    }
    const float bias1 = b_ih1[jj] + b_hh1[jj];

    // state registers: at loop head h0x = h0(t-1), h1x = h1(t-2)
    float h00, h01, h02, h03, h04, h10, h11, h12, h13, h14;
    {
        const int bb = bval ? b : 0;
        h00 = hx[bb * 5 + 0]; h01 = hx[bb * 5 + 1]; h02 = hx[bb * 5 + 2];
        h03 = hx[bb * 5 + 3]; h04 = hx[bb * 5 + 4];
        h10 = hx[B_SZ * 5 + bb * 5 + 0]; h11 = hx[B_SZ * 5 + bb * 5 + 1];
        h12 = hx[B_SZ * 5 + bb * 5 + 2]; h13 = hx[B_SZ * 5 + bb * 5 + 3];
        h14 = hx[B_SZ * 5 + bb * 5 + 4];
    }

    const float* pre0p = g_pre0 + (bval ? b : 0) * 5 + jj;
    float*       outp  = out + b * 5 + j;

    // pre0 prefetch queue, slot p holds pre0(t)_j with t&7 == p
    float pq[8];
    #pragma unroll
    for (int p = 0; p < 8; p++) pq[p] = pre0p[p * OSTRIDE];

    float h0j = 0.f, h1j = 0.f;

#define READBACK(BP) {                                                        \
    const float4 qa = *(const float4*)&buf[BP][g][0];                         \
    const float4 qb = *(const float4*)&buf[BP][g][4];                         \
    const float2 qc = *(const float2*)&buf[BP][g][8];                         \
    h00 = qa.x; h10 = qa.y; h01 = qa.z; h11 = qa.w;                           \
    h02 = qb.x; h12 = qb.y; h03 = qb.z; h13 = qb.w;                           \
    h04 = qc.x; h14 = qc.y;                                                   \
}

// One pipelined step t: h0(t) and h1(t-1). XP == t&7, BP == t&1 (literals).
#define STEP(t, XP, BP) {                                                     \
    /* layer-0 pre-activation: pre0 + wh0 . h0(t-1) */                        \
    const float p1 = fmaf(wh0[0], h00, pq[XP]);                               \
    const float p2 = fmaf(wh0[2], h02, wh0[1] * h01);                         \
    const float p3 = fmaf(wh0[4], h04, wh0[3] * h03);                         \
    const float s  = p1 + (p2 + p3);                                          \
    /* layer-1 pre-activation: bias1 + wi1 . h0(t-1) + wh1 . h1(t-2) */       \
    const float q1 = fmaf(wi1[0], h00, bias1);                                \
    const float q2 = fmaf(wi1[2], h02, wi1[1] * h01);                         \
    const float q3 = fmaf(wi1[4], h04, wi1[3] * h03);                         \
    const float q4 = fmaf(wh1[1], h11, wh1[0] * h10);                         \
    const float q5 = fmaf(wh1[4], h14, fmaf(wh1[3], h13, wh1[2] * h12));      \
    const float u  = (q1 + q2) + (q3 + q4) + q5;                              \
    h0j = tanh_fast(s);                                                       \
    h1j = tanh_fast(u);                                                       \
    *(float2*)&buf[BP][g][2 * j] = make_float2(h0j, h1j);                     \
    if (bval && (t) + 8 < T_LEN) pq[XP] = pre0p[((t) + 8) * OSTRIDE];         \
    if (act) outp[((t) - 1) * OSTRIDE] = h1j;                                 \
    __syncwarp();                                                             \
    READBACK(BP);                                                             \
}

    // ---- prologue t = 0: h0(0); republish h1(-1)=hx1 in the pair ----
    {
        const float p1 = fmaf(wh0[0], h00, pq[0]);
        const float p2 = fmaf(wh0[2], h02, wh0[1] * h01);
        const float p3 = fmaf(wh0[4], h04, wh0[3] * h03);
        h0j = tanh_fast(p1 + (p2 + p3));
        const float h1self = (jj == 0) ? h10 : (jj == 1) ? h11 :
                             (jj == 2) ? h12 : (jj == 3) ? h13 : h14;
        *(float2*)&buf[0][g][2 * j] = make_float2(h0j, h1self);
        if (bval) pq[0] = pre0p[8 * OSTRIDE];
        __syncwarp();
        READBACK(0);
    }

    // ---- main loop: t = 1 .. 2040 (t0 = 8m+1) ----
    for (int t0 = 1; t0 < 2041; t0 += 8) {
        STEP(t0 + 0, 1, 1);
        STEP(t0 + 1, 2, 0);
        STEP(t0 + 2, 3, 1);
        STEP(t0 + 3, 4, 0);
        STEP(t0 + 4, 5, 1);
        STEP(t0 + 5, 6, 0);
        STEP(t0 + 6, 7, 1);
        STEP(t0 + 7, 0, 0);
    }
    // ---- tail: t = 2041 .. 2047 ----
    STEP(2041, 1, 1);
    STEP(2042, 2, 0);
    STEP(2043, 3, 1);
    STEP(2044, 4, 0);
    STEP(2045, 5, 1);
    STEP(2046, 6, 0);
    STEP(2047, 7, 1);

    // ---- epilogue: h1(2047) from h0x=h0(2047), h1x=h1(2046) ----
    {
        const float q1 = fmaf(wi1[0], h00, bias1);
        const float q2 = fmaf(wi1[2], h02, wi1[1] * h01);
        const float q3 = fmaf(wi1[4], h04, wi1[3] * h03);
        const float q4 = fmaf(wh1[1], h11, wh1[0] * h10);
        const float q5 = fmaf(wh1[4], h14, fmaf(wh1[3], h13, wh1[2] * h12));
        h1j = tanh_fast((q1 + q2) + (q3 + q4) + q5);
        const float h0self = (jj == 0) ? h00 : (jj == 1) ? h01 :
                             (jj == 2) ? h02 : (jj == 3) ? h03 : h04;
        if (act) {
            outp[(T_LEN - 1) * OSTRIDE]              = h1j;     // out[2047]
            outp[(size_t)T_LEN * OSTRIDE]            = h0self;  // h_n[0]
            outp[(size_t)T_LEN * OSTRIDE + OSTRIDE]  = h1j;     // h_n[1]
        }
    }
#undef STEP
#undef READBACK
}

extern "C" void kernel_launch(void* const* d_in, const int* in_sizes, int n_in,
                              void* d_out, int out_size)
{
    const float* x     = (const float*)d_in[0];
    const float* hx    = (const float*)d_in[1];
    const float* w_ih0 = (const float*)d_in[2];
    const float* w_hh0 = (const float*)d_in[3];
    const float* b_ih0 = (const float*)d_in[4];
    const float* b_hh0 = (const float*)d_in[5];
    const float* w_ih1 = (const float*)d_in[6];
    const float* w_hh1 = (const float*)d_in[7];
    const float* b_ih1 = (const float*)d_in[8];
    const float* b_hh1 = (const float*)d_in[9];
    float* out = (float*)d_out;

    // A: 2048*4096/4 threads = 8192 blocks x 256
    pre0_kernel<<<8192, 256>>>(x, w_ih0, b_ih0, b_hh0);
    // B: R3 geometry, 147 blocks x 224 (1029 warps)
    rnn_rec_kernel<<<147, 224>>>(hx, w_hh0, w_ih1, w_hh1, b_ih1, b_hh1, out);
}

// round 11
// speedup vs baseline: 2.0579x; 1.2695x over previous
#include <cuda_runtime.h>
#include <cstdint>

// MultiLayerRNNModel: 2-layer tanh RNN, T=2048, B=4096, I=3, H=5
// out = concat(out[T,B,H], h_n[2,B,H])
//
// R11: R3 geometry (8 lanes/batch, 147x224, 1024+ warps), but the per-step
// __syncwarp is REMOVED. Within one warp, STS and LDS are warp-wide
// instructions the LSU processes in program order, so a later LDS sees an
// earlier STS from any lane without a barrier. Both are asm volatile (no
// compiler reordering); all divergent code (predicated STG/LDG) sits after
// the STS, so ITS runahead lanes still read valid data.
// Comm: one STS.64 pair (h0j,h1j), readback 2xLDS.128 + LDS.64 at literal
// offsets, double-buffered on t&1. Layers software-pipelined:
// step t computes h0(t) and h1(t-1).

#define T_LEN   2048
#define B_SZ    4096
#define XSTRIDE (B_SZ * 3)
#define OSTRIDE (B_SZ * 5)

__device__ __forceinline__ float tanh_fast(float v) {
    float y;
    asm("tanh.approx.f32 %0, %1;" : "=f"(y) : "f"(v));
    return y;
}
__device__ __forceinline__ void sts64(uint32_t a, float x0, float x1) {
    asm volatile("st.shared.v2.f32 [%0], {%1, %2};"
                 :: "r"(a), "f"(x0), "f"(x1));
}
__device__ __forceinline__ void lds128(uint32_t a, float& x0, float& x1,
                                       float& x2, float& x3) {
    asm volatile("ld.shared.v4.f32 {%0, %1, %2, %3}, [%4];"
                 : "=f"(x0), "=f"(x1), "=f"(x2), "=f"(x3) : "r"(a));
}
__device__ __forceinline__ void lds64(uint32_t a, float& x0, float& x1) {
    asm volatile("ld.shared.v2.f32 {%0, %1}, [%2];"
                 : "=f"(x0), "=f"(x1) : "r"(a));
}

__global__ __launch_bounds__(224, 1)
void rnn2_kernel(const float* __restrict__ x,
                 const float* __restrict__ hx,
                 const float* __restrict__ w_ih0,
                 const float* __restrict__ w_hh0,
                 const float* __restrict__ b_ih0,
                 const float* __restrict__ b_hh0,
                 const float* __restrict__ w_ih1,
                 const float* __restrict__ w_hh1,
                 const float* __restrict__ b_ih1,
                 const float* __restrict__ b_hh1,
                 float* __restrict__ out)
{
    // Slot layout (20-float stride): [2k]=h0_k, [2k+1]=h1_k (k=0..4),
    // [10..19] pad (lanes j>=5 write there). Read bases of the warp's 4
    // groups land on banks {0,20,8,28} (+4, +8 for the other vectors):
    // conflict-free broadcast reads.
    __shared__ __align__(16) float buf[2][28][20];

    const int tid = blockIdx.x * 224 + threadIdx.x;
    const int b   = tid >> 3;
    const int j   = threadIdx.x & 7;
    const int g   = threadIdx.x >> 3;
    const bool bval = (b < B_SZ);
    const bool act  = bval && (j < 5);
    const int  jj   = (j < 5) ? j : 0;

    // per-lane weights (row jj)
    float wi0[3], wh0[5], wi1[5], wh1[5];
    #pragma unroll
    for (int k = 0; k < 3; k++) wi0[k] = w_ih0[jj * 3 + k];
    #pragma unroll
    for (int k = 0; k < 5; k++) {
        wh0[k] = w_hh0[jj * 5 + k];
        wi1[k] = w_ih1[jj * 5 + k];
        wh1[k] = w_hh1[jj * 5 + k];
    }
    const float bias0 = b_ih0[jj] + b_hh0[jj];
    const float bias1 = b_ih1[jj] + b_hh1[jj];

    // replicated state: at loop head h0x = h0(t-1), h1x = h1(t-2)
    float h00, h01, h02, h03, h04, h10, h11, h12, h13, h14;
    {
        const int bb = bval ? b : 0;
        h00 = hx[bb * 5 + 0]; h01 = hx[bb * 5 + 1]; h02 = hx[bb * 5 + 2];
        h03 = hx[bb * 5 + 3]; h04 = hx[bb * 5 + 4];
        h10 = hx[B_SZ * 5 + bb * 5 + 0]; h11 = hx[B_SZ * 5 + bb * 5 + 1];
        h12 = hx[B_SZ * 5 + bb * 5 + 2]; h13 = hx[B_SZ * 5 + bb * 5 + 3];
        h14 = hx[B_SZ * 5 + bb * 5 + 4];
    }

    const float* xb   = x + b * 3;
    float*       outp = out + b * 5 + j;

    const uint32_t base0 = (uint32_t)__cvta_generic_to_shared(&buf[0][g][0]);
    const uint32_t wa    = base0 + 8u * (uint32_t)j;     // own pair cell
    const uint32_t PARB  = 28u * 20u * 4u;               // parity stride (B)

    // x prefetch queue, slot p holds x(t) with t&7 == p
    float xq[8][3];
    #pragma unroll
    for (int p = 0; p < 8; p++) {
        const float* xp = xb + p * XSTRIDE;
        xq[p][0] = bval ? xp[0] : 0.f;
        xq[p][1] = bval ? xp[1] : 0.f;
        xq[p][2] = bval ? xp[2] : 0.f;
    }

// One pipelined step t: h0(t) and h1(t-1). XP == t&7, BP == t&1 (literals).
// No __syncwarp: asm-volatile STS then LDS, warp-wide in-order LSU.
#define STEP(t, XP, BP) {                                                     \
    /* layer-0 pre-activation: x-proj off the h-critical path */              \
    const float pre = fmaf(wi0[2], xq[XP][2],                                 \
                      fmaf(wi0[1], xq[XP][1],                                 \
                      fmaf(wi0[0], xq[XP][0], bias0)));                       \
    const float a0 = fmaf(wh0[0], h00, pre);                                  \
    const float a1 = fmaf(wh0[2], h02, wh0[1] * h01);                         \
    const float a2 = fmaf(wh0[4], h04, wh0[3] * h03);                         \
    const float s  = a0 + (a1 + a2);                                          \
    /* layer-1 pre-activation for h1(t-1) */                                  \
    const float q1 = fmaf(wi1[0], h00, bias1);                                \
    const float q2 = fmaf(wi1[2], h02, wi1[1] * h01);                         \
    const float q3 = fmaf(wi1[4], h04, wi1[3] * h03);                         \
    const float q4 = fmaf(wh1[1], h11, wh1[0] * h10);                         \
    const float q5 = fmaf(wh1[4], h14, fmaf(wh1[3], h13, wh1[2] * h12));      \
    const float u  = (q1 + q2) + (q3 + q4) + q5;                              \
    const float h0j = tanh_fast(s);                                           \
    const float h1j = tanh_fast(u);                                           \
    sts64(wa + (BP) * PARB, h0j, h1j);                                        \
    lds128(base0 + (BP) * PARB,      h00, h10, h01, h11);                     \
    lds128(base0 + (BP) * PARB + 16, h02, h12, h03, h13);                     \
    lds64 (base0 + (BP) * PARB + 32, h04, h14);                               \
    if (bval && (t) + 8 < T_LEN) {                                            \
        const float* xp = xb + ((t) + 8) * XSTRIDE;                           \
        xq[XP][0] = xp[0]; xq[XP][1] = xp[1]; xq[XP][2] = xp[2];              \
    }                                                                         \
    if (act) outp[((t) - 1) * OSTRIDE] = h1j;                                 \
}

    // ---- prologue t = 0: h0(0); republish h1(-1)=hx1 in the pair ----
    {
        const float pre = fmaf(wi0[2], xq[0][2],
                          fmaf(wi0[1], xq[0][1],
                          fmaf(wi0[0], xq[0][0], bias0)));
        const float a0 = fmaf(wh0[0], h00, pre);
        const float a1 = fmaf(wh0[2], h02, wh0[1] * h01);
        const float a2 = fmaf(wh0[4], h04, wh0[3] * h03);
        const float h0j = tanh_fast(a0 + (a1 + a2));
        const float h1self = (jj == 0) ? h10 : (jj == 1) ? h11 :
                             (jj == 2) ? h12 : (jj == 3) ? h13 : h14;
        sts64(wa, h0j, h1self);
        lds128(base0,      h00, h10, h01, h11);
        lds128(base0 + 16, h02, h12, h03, h13);
        lds64 (base0 + 32, h04, h14);
        if (bval) {
            const float* xp = xb + 8 * XSTRIDE;
            xq[0][0] = xp[0]; xq[0][1] = xp[1]; xq[0][2] = xp[2];
        }
    }

    // ---- main loop: t = 1 .. 2040 (t0 = 8m+1) ----
    for (int t0 = 1; t0 < 2041; t0 += 8) {
        STEP(t0 + 0, 1, 1);
        STEP(t0 + 1, 2, 0);
        STEP(t0 + 2, 3, 1);
        STEP(t0 + 3, 4, 0);
        STEP(t0 + 4, 5, 1);
        STEP(t0 + 5, 6, 0);
        STEP(t0 + 6, 7, 1);
        STEP(t0 + 7, 0, 0);
    }
    // ---- tail: t = 2041 .. 2047 ----
    STEP(2041, 1, 1);
    STEP(2042, 2, 0);
    STEP(2043, 3, 1);
    STEP(2044, 4, 0);
    STEP(2045, 5, 1);
    STEP(2046, 6, 0);
    STEP(2047, 7, 1);

    // ---- epilogue: h1(2047) from h0x=h0(2047), h1x=h1(2046) ----
    {
        const float q1 = fmaf(wi1[0], h00, bias1);
        const float q2 = fmaf(wi1[2], h02, wi1[1] * h01);
        const float q3 = fmaf(wi1[4], h04, wi1[3] * h03);
        const float q4 = fmaf(wh1[1], h11, wh1[0] * h10);
        const float q5 = fmaf(wh1[4], h14, fmaf(wh1[3], h13, wh1[2] * h12));
        const float h1j = tanh_fast((q1 + q2) + (q3 + q4) + q5);
        const float h0self = (jj == 0) ? h00 : (jj == 1) ? h01 :
                             (jj == 2) ? h02 : (jj == 3) ? h03 : h04;
        if (act) {
            outp[(T_LEN - 1) * OSTRIDE]             = h1j;     // out[2047]
            outp[(size_t)T_LEN * OSTRIDE]           = h0self;  // h_n[0]
            outp[(size_t)T_LEN * OSTRIDE + OSTRIDE] = h1j;     // h_n[1]
        }
    }
#undef STEP
}

extern "C" void kernel_launch(void* const* d_in, const int* in_sizes, int n_in,
                              void* d_out, int out_size)
{
    const float* x     = (const float*)d_in[0];
    const float* hx    = (const float*)d_in[1];
    const float* w_ih0 = (const float*)d_in[2];
    const float* w_hh0 = (const float*)d_in[3];
    const float* b_ih0 = (const float*)d_in[4];
    const float* b_hh0 = (const float*)d_in[5];
    const float* w_ih1 = (const float*)d_in[6];
    const float* w_hh1 = (const float*)d_in[7];
    const float* b_ih1 = (const float*)d_in[8];
    const float* b_hh1 = (const float*)d_in[9];
    float* out = (float*)d_out;

    const int threads = 224;                                 // 7 warps
    const int blocks  = (B_SZ * 8 + threads - 1) / threads;  // 147

    rnn2_kernel<<<blocks, threads>>>(x, hx, w_ih0, w_hh0, b_ih0, b_hh0,
                                     w_ih1, w_hh1, b_ih1, b_hh1, out);
}